// round 10
// baseline (speedup 1.0000x reference)
#include <cuda_runtime.h>

// SampleQueryExtractionLayer: bilinear-style 4-tap gather (converged optimum).
// features: [B=4, N=4096(=64x64), C=256] fp32; query_points: [4,8,256,2];
// out: [8192, 256] fp32.
//
// Structure proven best over 9 rounds: single wave (4096 x 64-thread CTAs,
// exactly 32 regs -> full RF at 64 warps/SM), each CTA handles TWO ADJACENT
// queries sequentially so gather data regs are reused. Both query points
// arrive in ONE float4 load (adjacent queries share a 16B line), so hop 1 is
// a single broadcast LDG. Weight math (incl. MUFU) stays off the address
// path; evict-first stores keep features L2-resident across graph replays.
// Runtime is dominated by fixed launch/distribution overhead (~5000 cyc) at
// DVFS-floor clocks; per-thread work is fully latency-shadowed.

#define EPS_F 0.0001f

__device__ __forceinline__ void do_query(const float* __restrict__ feat,
                                         float* __restrict__ out,
                                         float py, float px, int g, int c4)
{
    const int y0 = __float2int_rd(py);
    const int x0 = __float2int_rd(px);
    const int b  = g >> 11;                      // 2048 queries per batch

    const float4* r00 = (const float4*)feat
                        + (size_t)(b * 4096 + y0 * 64 + x0) * 64 + c4;
    // 4 independent gathers, front-batched.
    const float4 f00 = __ldg(r00);
    const float4 f01 = __ldg(r00 + 64);          // (y0, x0+1)
    const float4 f10 = __ldg(r00 + 64 * 64);     // (y0+1, x0)
    const float4 f11 = __ldg(r00 + 64 * 65);     // (y0+1, x0+1)

    // Weight math overlaps the gather latency.
    const float dy = py - (float)y0;
    const float dx = px - (float)x0;
    const float m00 = fmaxf(0.f, 1.f - (dy + dx)       + EPS_F);
    const float m01 = fmaxf(0.f, 1.f - (dy + 1.f - dx) + EPS_F);
    const float m10 = fmaxf(0.f, 1.f - (1.f - dy + dx) + EPS_F);
    const float m11 = fmaxf(0.f, 1.f - (2.f - dy - dx) + EPS_F);
    const float w00 = m00 * m00;
    const float w01 = m01 * m01;
    const float w10 = m10 * m10;
    const float w11 = m11 * m11;
    const float inv = __fdividef(1.f, w00 + w01 + w10 + w11 + EPS_F);

    float4 acc;
    acc.x = (w00*f00.x + w01*f01.x + w10*f10.x + w11*f11.x) * inv;
    acc.y = (w00*f00.y + w01*f01.y + w10*f10.y + w11*f11.y) * inv;
    acc.z = (w00*f00.z + w01*f01.z + w10*f10.z + w11*f11.z) * inv;
    acc.w = (w00*f00.w + w01*f01.w + w10*f10.w + w11*f11.w) * inv;

    // Evict-first store: keep the feature matrix resident in L2.
    __stcs(((float4*)out) + (size_t)g * 64 + c4, acc);
}

__global__ __launch_bounds__(64)
void sqe_kernel(const float* __restrict__ feat,
                const float* __restrict__ qp,
                float* __restrict__ out)
{
    const int c4  = threadIdx.x;                 // 0..63, float4 lane in C
    const int grp = blockIdx.x;                  // 0..4095

    const int q0 = grp * 2;                      // adjacent queries, same batch
    const int q1 = q0 + 1;

    // ONE 16B load fetches both query points (broadcast within the block).
    const float4 pp = __ldg(((const float4*)qp) + grp);

    do_query(feat, out, pp.x, pp.y, q0, c4);
    do_query(feat, out, pp.z, pp.w, q1, c4);
}

extern "C" void kernel_launch(void* const* d_in, const int* in_sizes, int n_in,
                              void* d_out, int out_size)
{
    (void)in_sizes; (void)n_in; (void)out_size;
    const float* feat = (const float*)d_in[0];
    const float* qp   = (const float*)d_in[1];
    float* out        = (float*)d_out;

    // 4096 groups x 2 adjacent queries = 8192 queries, single wave.
    sqe_kernel<<<4096, 64>>>(feat, qp, out);
}